// round 14
// baseline (speedup 1.0000x reference)
#include <cuda_runtime.h>
#include <cuda_fp16.h>
#include <math.h>
#include <stdint.h>

#define B_ROWS 8192
#define D_DIM  1024
#define NTHREADS_SCAN 1024

// ---------------- scratch (static device globals) ---------------------------
__device__ int   g_M;
__device__ int   g_sel[B_ROWS];
__device__ __align__(16) int g_lab[B_ROWS];
__device__ __align__(128) __half g_f16[(size_t)B_ROWS * D_DIM];         // 16 MB
__device__ __align__(128) float g_sim[(size_t)B_ROWS * (size_t)B_ROWS];
__device__ float g_rowloss[B_ROWS];

__device__ __forceinline__ uint32_t smem_u32(const void* p) {
    uint32_t a;
    asm("{ .reg .u64 t; cvta.to.shared.u64 t, %1; cvt.u32.u64 %0, t; }" : "=r"(a) : "l"(p));
    return a;
}

// ---------------- kernel 0: select + compaction (parallel dtype probe) -------
__global__ void __launch_bounds__(NTHREADS_SCAN)
k_select(const float* __restrict__ score, const void* __restrict__ labels_raw,
         const int* __restrict__ type_idx_p)
{
    const int t = threadIdx.x;
    const int lane = t & 31;
    const int w = t >> 5;
    __shared__ int s_is64;
    __shared__ int wsum[32];

    // parallel int64-vs-int32 probe: 64 threads test odd 32-bit words at once
    if (t == 0) s_is64 = 1;
    __syncthreads();
    if (t < 64 && ((const int*)labels_raw)[2 * t + 1] != 0) s_is64 = 0;

    float v[24];
    {
        const float4* s4p = (const float4*)score + 6 * t;
#pragma unroll
        for (int q = 0; q < 6; q++) {
            float4 x = __ldg(s4p + q);
            v[q * 4 + 0] = x.x; v[q * 4 + 1] = x.y; v[q * 4 + 2] = x.z; v[q * 4 + 3] = x.w;
        }
    }
    __syncthreads();
    const int is64 = s_is64;
    const int ti = type_idx_p[0];

    int flags[8], lab8[8], loc = 0;
#pragma unroll
    for (int q = 0; q < 8; q++) {
        int i = t * 8 + q;
        float s0 = v[3 * q], s1 = v[3 * q + 1], s2 = v[3 * q + 2];
        int am = 0; float b = s0;
        if (s1 > b) { b = s1; am = 1; }
        if (s2 > b) { b = s2; am = 2; }
        flags[q] = (am == ti) ? 1 : 0;
        if (is64) lab8[q] = (int)(((const long long*)labels_raw)[i]);
        else      lab8[q] = ((const int*)labels_raw)[i];
        loc += flags[q];
    }

    int incl = loc;
#pragma unroll
    for (int o = 1; o < 32; o <<= 1) {
        int x = __shfl_up_sync(0xffffffffu, incl, o);
        if (lane >= o) incl += x;
    }
    if (lane == 31) wsum[w] = incl;
    __syncthreads();
    if (w == 0) {
        int x = wsum[lane];
        int sx = x;
#pragma unroll
        for (int o = 1; o < 32; o <<= 1) {
            int y = __shfl_up_sync(0xffffffffu, sx, o);
            if (lane >= o) sx += y;
        }
        wsum[lane] = sx - x;
    }
    __syncthreads();
    int pos = wsum[w] + incl - loc;
#pragma unroll
    for (int q = 0; q < 8; q++) {
        int i = t * 8 + q;
        if (flags[q]) { g_sel[pos] = i; g_lab[pos] = lab8[q]; pos++; }
    }
    if (t == NTHREADS_SCAN - 1) g_M = wsum[31] + incl;
}

// ---------------- kernel 1: gather + L2 normalize + fp16 ---------------------
__global__ void __launch_bounds__(256)
k_normalize(const float* __restrict__ feats)
{
    const int j = blockIdx.x;
    const int M = g_M;
    const int Mpad = (M + 127) & ~127;
    if (j >= Mpad) return;
    const int t = threadIdx.x;

    if (j >= M) {
        ((uint2*)(g_f16 + (size_t)j * D_DIM))[t] = make_uint2(0, 0);
        if (t == 0) g_lab[j] = 0x80000000;
        return;
    }
    const int src = g_sel[j];
    const float4 a = ((const float4*)(feats + (size_t)src * D_DIM))[t];
    float ss = a.x * a.x + a.y * a.y + a.z * a.z + a.w * a.w;

    __shared__ float red[256];
    red[t] = ss;
    __syncthreads();
    for (int off = 128; off > 0; off >>= 1) {
        if (t < off) red[t] += red[t + off];
        __syncthreads();
    }
    const float inv = 1.0f / fmaxf(sqrtf(red[0]), 1e-12f);

    __half h[4];
    h[0] = __float2half_rn(a.x * inv);
    h[1] = __float2half_rn(a.y * inv);
    h[2] = __float2half_rn(a.z * inv);
    h[3] = __float2half_rn(a.w * inv);
    uint2 hp;
    hp.x = (uint32_t)(*(uint16_t*)&h[0]) | ((uint32_t)(*(uint16_t*)&h[1]) << 16);
    hp.y = (uint32_t)(*(uint16_t*)&h[2]) | ((uint32_t)(*(uint16_t*)&h[3]) << 16);
    ((uint2*)(g_f16 + (size_t)j * D_DIM))[t] = hp;
}

// ---------------- kernel 2: fp16 single-product GEMM (symmetric tiles) -------
#define TILE 128
#define KC 64
#define NCHUNK (D_DIM / KC)                   // 16
#define TILE_BYTES (TILE * 128)               // 16384
#define STAGE_BYTES (2 * TILE_BYTES)          // 32768 (A,B)
#define NSTAGE 3
#define GEMM_SMEM (NSTAGE * STAGE_BYTES)      // 98304 -> 2 CTAs/SM
#define PAD_SENTINEL -1e30f

__device__ __forceinline__ void ldsm4(uint32_t* r, uint32_t addr) {
    asm volatile("ldmatrix.sync.aligned.m8n8.x4.shared.b16 {%0,%1,%2,%3}, [%4];"
                 : "=r"(r[0]), "=r"(r[1]), "=r"(r[2]), "=r"(r[3]) : "r"(addr));
}
__device__ __forceinline__ void mma16816h(float* d, const uint32_t* a, const uint32_t* b) {
    asm volatile(
        "mma.sync.aligned.m16n8k16.row.col.f32.f16.f16.f32 "
        "{%0,%1,%2,%3}, {%4,%5,%6,%7}, {%8,%9}, {%0,%1,%2,%3};"
        : "+f"(d[0]), "+f"(d[1]), "+f"(d[2]), "+f"(d[3])
        : "r"(a[0]), "r"(a[1]), "r"(a[2]), "r"(a[3]), "r"(b[0]), "r"(b[1]));
}

__global__ void __launch_bounds__(256, 2)
k_gemm()
{
    const int M = g_M;
    const int tiles = (M + 127) >> 7;
    const int bx = blockIdx.x, by = blockIdx.y;
    if (by >= tiles || bx > by) return;
    const int ldm = tiles << 7;
    const int rt = by * TILE;
    const int ct = bx * TILE;
    const int tid = threadIdx.x;
    const int lane = tid & 31;
    const int wid = tid >> 5;
    const int wm = wid >> 1;
    const int wn = wid & 1;

    extern __shared__ __align__(1024) char smc[];
    const uint32_t tb = smem_u32(smc);

    auto load_chunk = [&](int kc, int stage) {
        const uint32_t sb = tb + stage * STAGE_BYTES;
        const int kb = kc * KC;
#pragma unroll
        for (int i = 0; i < 8; i++) {
            const int c = tid + i * 256;
            const int tix = c >> 10;
            const int r   = (c >> 3) & 127;
            const int seg = c & 7;
            const __half* src = g_f16 + (size_t)((tix ? ct : rt) + r) * D_DIM + kb + seg * 8;
            uint32_t dst = sb + tix * TILE_BYTES + r * 128 + ((seg ^ (r & 7)) << 4);
            asm volatile("cp.async.cg.shared.global [%0], [%1], 16;" :: "r"(dst), "l"(src));
        }
        asm volatile("cp.async.commit_group;");
    };

    float acc[2][8][4];
#pragma unroll
    for (int mf = 0; mf < 2; mf++)
#pragma unroll
        for (int nf = 0; nf < 8; nf++)
#pragma unroll
            for (int i = 0; i < 4; i++) acc[mf][nf][i] = 0.0f;

    load_chunk(0, 0);
    load_chunk(1, 1);
    load_chunk(2, 2);

    for (int k = 0; k < NCHUNK; k++) {
        if (k + 3 <= NCHUNK)      asm volatile("cp.async.wait_group 2;" ::: "memory");
        else if (k + 2 == NCHUNK) asm volatile("cp.async.wait_group 1;" ::: "memory");
        else                      asm volatile("cp.async.wait_group 0;" ::: "memory");
        __syncthreads();

        const int st = k % NSTAGE;
        const uint32_t A = tb + st * STAGE_BYTES;
        const uint32_t B = A + TILE_BYTES;

#pragma unroll
        for (int ks = 0; ks < 4; ks++) {
            uint32_t ah[2][4];
#pragma unroll
            for (int mf = 0; mf < 2; mf++) {
                const int row = wm * 32 + mf * 16 + (lane & 15);
                const int seg = ks * 2 + (lane >> 4);
                ldsm4(ah[mf], A + row * 128 + ((seg ^ (row & 7)) << 4));
            }
            uint32_t bh[4][4];
#pragma unroll
            for (int nq = 0; nq < 4; nq++) {
                const int row = wn * 64 + nq * 16 + (lane & 7) + ((lane >> 4) << 3);
                const int seg = ks * 2 + ((lane >> 3) & 1);
                ldsm4(bh[nq], B + row * 128 + ((seg ^ (row & 7)) << 4));
            }
#pragma unroll
            for (int mf = 0; mf < 2; mf++)
#pragma unroll
                for (int nf = 0; nf < 8; nf++)
                    mma16816h(acc[mf][nf], ah[mf], &bh[nf >> 1][(nf & 1) * 2]);
        }
        __syncthreads();
        if (k + 3 < NCHUNK) load_chunk(k + 3, st);
    }

#pragma unroll
    for (int mf = 0; mf < 2; mf++)
#pragma unroll
        for (int nf = 0; nf < 8; nf++) {
            const int r0 = rt + wm * 32 + mf * 16 + (lane >> 2);
            const int c0 = ct + wn * 64 + nf * 8 + (lane & 3) * 2;
            float v0 = (c0     >= M) ? PAD_SENTINEL : acc[mf][nf][0];
            float v1 = (c0 + 1 >= M) ? PAD_SENTINEL : acc[mf][nf][1];
            float v2 = (c0     >= M) ? PAD_SENTINEL : acc[mf][nf][2];
            float v3 = (c0 + 1 >= M) ? PAD_SENTINEL : acc[mf][nf][3];
            *(float2*)(g_sim + (size_t)r0 * ldm + c0)       = make_float2(v0, v1);
            *(float2*)(g_sim + (size_t)(r0 + 8) * ldm + c0) = make_float2(v2, v3);
        }

    if (bx == by) {
        __syncthreads();
        if (tid < 128) {
            const int d = rt + tid;
            if (d < M) g_sim[(size_t)d * ldm + d] = 1.0f;
        }
    } else {
        float* S = (float*)smc;      // [128][136]
#pragma unroll
        for (int mf = 0; mf < 2; mf++)
#pragma unroll
            for (int nf = 0; nf < 8; nf++) {
                const int rl = wm * 32 + mf * 16 + (lane >> 2);
                const int cl = wn * 64 + nf * 8 + (lane & 3) * 2;
                S[cl * 136 + rl]           = acc[mf][nf][0];
                S[(cl + 1) * 136 + rl]     = acc[mf][nf][1];
                S[cl * 136 + rl + 8]       = acc[mf][nf][2];
                S[(cl + 1) * 136 + rl + 8] = acc[mf][nf][3];
            }
        __syncthreads();
        for (int i = tid; i < 128 * 32; i += 256) {
            const int row = i >> 5;
            const int c4  = (i & 31) * 4;
            float4 v = make_float4(S[row * 136 + c4], S[row * 136 + c4 + 1],
                                   S[row * 136 + c4 + 2], S[row * 136 + c4 + 3]);
            if (rt + c4     >= M) v.x = PAD_SENTINEL;
            if (rt + c4 + 1 >= M) v.y = PAD_SENTINEL;
            if (rt + c4 + 2 >= M) v.z = PAD_SENTINEL;
            if (rt + c4 + 3 >= M) v.w = PAD_SENTINEL;
            *(float4*)(g_sim + (size_t)(ct + row) * ldm + rt + c4) = v;
        }
    }
}

// ---------------- kernel 3: per-row epilogue (R10 measured-best) -------------
__global__ void __launch_bounds__(256)
k_rowloss()
{
    const int M = g_M;
    if ((int)blockIdx.x * 2 >= M) return;
    const int Mpad = (M + 127) & ~127;
    const int Mpad4 = Mpad >> 2;
    const int t = threadIdx.x;
    const int lane = t & 31;
    const int wid = t >> 5;          // 0..7
    const int grp = wid >> 2;        // 0..1 : row group
    const int gtid = t & 127;        // 0..127 within group
    const int r = blockIdx.x * 2 + grp;
    const bool active = (r < M);

    __shared__ float sm_min[8], sm_max[8], sm_p[8], sm_n[8];
    __shared__ int sm_cnt[8];

    const int labr = active ? __ldg(&g_lab[r]) : 0;
    const float4* __restrict__ row4 = (const float4*)(g_sim + (size_t)r * (size_t)Mpad);
    const int4* __restrict__ lab4 = (const int4*)g_lab;
    const float INF = __int_as_float(0x7f800000);
    const float C1 = 1.0f - 1e-5f;

    // pass 1 (guard-free inner: exact 1.0 diagonal; sentinel pads/labels)
    float minpos = INF, maxneg = -INF;
    int cnt = 0;
    if (active) {
        for (int q = gtid; q < Mpad4; q += 128) {
            const float4 sv = __ldg(row4 + q);
            const int4 lv = __ldg(lab4 + q);
            const bool b0 = (lv.x == labr), b1 = (lv.y == labr);
            const bool b2 = (lv.z == labr), b3 = (lv.w == labr);
            cnt += (int)b0 + (int)b1 + (int)b2 + (int)b3;
            minpos = fminf(minpos, (b0 && sv.x < C1) ? sv.x : INF);
            minpos = fminf(minpos, (b1 && sv.y < C1) ? sv.y : INF);
            minpos = fminf(minpos, (b2 && sv.z < C1) ? sv.z : INF);
            minpos = fminf(minpos, (b3 && sv.w < C1) ? sv.w : INF);
            maxneg = fmaxf(maxneg, b0 ? -INF : sv.x);
            maxneg = fmaxf(maxneg, b1 ? -INF : sv.y);
            maxneg = fmaxf(maxneg, b2 ? -INF : sv.z);
            maxneg = fmaxf(maxneg, b3 ? -INF : sv.w);
        }
    }
#pragma unroll
    for (int o = 16; o; o >>= 1) {
        minpos = fminf(minpos, __shfl_xor_sync(0xffffffffu, minpos, o));
        maxneg = fmaxf(maxneg, __shfl_xor_sync(0xffffffffu, maxneg, o));
        cnt += __shfl_xor_sync(0xffffffffu, cnt, o);
    }
    if (lane == 0) { sm_min[wid] = minpos; sm_max[wid] = maxneg; sm_cnt[wid] = cnt; }
    __syncthreads();
    const int gb = grp * 4;
    float mp = INF, mn = -INF;
    int c = 0;
#pragma unroll
    for (int q = 0; q < 4; q++) {
        mp = fminf(mp, sm_min[gb + q]);
        mn = fmaxf(mn, sm_max[gb + q]);
        c += sm_cnt[gb + q];
    }
    const bool valid = active && (c > 1) && (mn > mp - 0.1f);

    // pass 2 (only valid rows do work; all threads reach the final sync)
    float psum = 0.f, nsum = 0.f;
    if (valid) {
        for (int q = gtid; q < Mpad4; q += 128) {
            const float4 sv = __ldg(row4 + q);
            const int4 lv = __ldg(lab4 + q);
            if (lv.x == labr) { if (sv.x < C1 && sv.x - 0.1f < mn) psum += __expf(-2.0f * (sv.x - 0.5f)); }
            else              { if (sv.x + 0.1f > mp)             nsum += __expf(40.0f * (sv.x - 0.5f)); }
            if (lv.y == labr) { if (sv.y < C1 && sv.y - 0.1f < mn) psum += __expf(-2.0f * (sv.y - 0.5f)); }
            else              { if (sv.y + 0.1f > mp)             nsum += __expf(40.0f * (sv.y - 0.5f)); }
            if (lv.z == labr) { if (sv.z < C1 && sv.z - 0.1f < mn) psum += __expf(-2.0f * (sv.z - 0.5f)); }
            else              { if (sv.z + 0.1f > mp)             nsum += __expf(40.0f * (sv.z - 0.5f)); }
            if (lv.w == labr) { if (sv.w < C1 && sv.w - 0.1f < mn) psum += __expf(-2.0f * (sv.w - 0.5f)); }
            else              { if (sv.w + 0.1f > mp)             nsum += __expf(40.0f * (sv.w - 0.5f)); }
        }
    }
#pragma unroll
    for (int o = 16; o; o >>= 1) {
        psum += __shfl_xor_sync(0xffffffffu, psum, o);
        nsum += __shfl_xor_sync(0xffffffffu, nsum, o);
    }
    if (lane == 0) { sm_p[wid] = psum; sm_n[wid] = nsum; }
    __syncthreads();
    if (active && gtid == 0) {
        if (!valid) {
            g_rowloss[r] = 0.0f;
        } else {
            float P = sm_p[gb] + sm_p[gb + 1] + sm_p[gb + 2] + sm_p[gb + 3];
            float N = sm_n[gb] + sm_n[gb + 1] + sm_n[gb + 2] + sm_n[gb + 3];
            g_rowloss[r] = log1pf(P) / 2.0f + log1pf(N) / 40.0f;
        }
    }
}

// ---------------- kernel 4: deterministic final sum --------------------------
__global__ void __launch_bounds__(256)
k_finalize(float* __restrict__ out)
{
    const int M = g_M;
    const int t = threadIdx.x;
    float acc = 0.f;
    for (int i = t; i < M; i += 256) acc += g_rowloss[i];
    __shared__ float red[256];
    red[t] = acc;
    __syncthreads();
    for (int off = 128; off > 0; off >>= 1) {
        if (t < off) red[t] += red[t + off];
        __syncthreads();
    }
    if (t == 0) out[0] = red[0] / (float)B_ROWS;
}

// ---------------- launcher ---------------------------------------------------
extern "C" void kernel_launch(void* const* d_in, const int* in_sizes, int n_in,
                              void* d_out, int out_size)
{
    const float* feats  = (const float*)d_in[0];
    const void*  labels = d_in[1];
    const float* score  = (const float*)d_in[2];
    const int*   tidx   = (const int*)d_in[3];
    float* out = (float*)d_out;

    cudaFuncSetAttribute(k_gemm, cudaFuncAttributeMaxDynamicSharedMemorySize, GEMM_SMEM);

    k_select<<<1, NTHREADS_SCAN>>>(score, labels, tidx);
    k_normalize<<<B_ROWS, 256>>>(feats);
    dim3 grid(B_ROWS / TILE, B_ROWS / TILE);
    k_gemm<<<grid, 256, GEMM_SMEM>>>();
    k_rowloss<<<B_ROWS / 2, 256>>>();
    k_finalize<<<1, 256>>>(out);
}

// round 15
// speedup vs baseline: 1.0297x; 1.0297x over previous
#include <cuda_runtime.h>
#include <cuda_fp16.h>
#include <math.h>
#include <stdint.h>

#define B_ROWS 8192
#define D_DIM  1024
#define NTHREADS_SCAN 1024

// ---------------- scratch (static device globals) ---------------------------
__device__ int   g_M;
__device__ int   g_sel[B_ROWS];
__device__ __align__(16) int g_lab[B_ROWS];
__device__ __align__(128) __half g_f16[(size_t)B_ROWS * D_DIM];         // 16 MB
__device__ __align__(128) float g_sim[(size_t)B_ROWS * (size_t)B_ROWS];
__device__ float g_rowloss[B_ROWS];

__device__ __forceinline__ uint32_t smem_u32(const void* p) {
    uint32_t a;
    asm("{ .reg .u64 t; cvta.to.shared.u64 t, %1; cvt.u32.u64 %0, t; }" : "=r"(a) : "l"(p));
    return a;
}

// ---------------- kernel 0: select + compaction -------------------------------
__global__ void __launch_bounds__(NTHREADS_SCAN)
k_select(const float* __restrict__ score, const void* __restrict__ labels_raw,
         const int* __restrict__ type_idx_p)
{
    const int t = threadIdx.x;
    const int lane = t & 31;
    const int w = t >> 5;
    __shared__ int s_is64;
    __shared__ int wsum[32];

    if (t == 0) s_is64 = 1;
    __syncthreads();
    if (t < 64 && ((const int*)labels_raw)[2 * t + 1] != 0) s_is64 = 0;

    float v[24];
    {
        const float4* s4p = (const float4*)score + 6 * t;
#pragma unroll
        for (int q = 0; q < 6; q++) {
            float4 x = __ldg(s4p + q);
            v[q * 4 + 0] = x.x; v[q * 4 + 1] = x.y; v[q * 4 + 2] = x.z; v[q * 4 + 3] = x.w;
        }
    }
    __syncthreads();
    const int is64 = s_is64;
    const int ti = type_idx_p[0];

    int flags[8], lab8[8], loc = 0;
#pragma unroll
    for (int q = 0; q < 8; q++) {
        int i = t * 8 + q;
        float s0 = v[3 * q], s1 = v[3 * q + 1], s2 = v[3 * q + 2];
        int am = 0; float b = s0;
        if (s1 > b) { b = s1; am = 1; }
        if (s2 > b) { b = s2; am = 2; }
        flags[q] = (am == ti) ? 1 : 0;
        if (is64) lab8[q] = (int)(((const long long*)labels_raw)[i]);
        else      lab8[q] = ((const int*)labels_raw)[i];
        loc += flags[q];
    }

    int incl = loc;
#pragma unroll
    for (int o = 1; o < 32; o <<= 1) {
        int x = __shfl_up_sync(0xffffffffu, incl, o);
        if (lane >= o) incl += x;
    }
    if (lane == 31) wsum[w] = incl;
    __syncthreads();
    if (w == 0) {
        int x = wsum[lane];
        int sx = x;
#pragma unroll
        for (int o = 1; o < 32; o <<= 1) {
            int y = __shfl_up_sync(0xffffffffu, sx, o);
            if (lane >= o) sx += y;
        }
        wsum[lane] = sx - x;
    }
    __syncthreads();
    int pos = wsum[w] + incl - loc;
#pragma unroll
    for (int q = 0; q < 8; q++) {
        int i = t * 8 + q;
        if (flags[q]) { g_sel[pos] = i; g_lab[pos] = lab8[q]; pos++; }
    }
    if (t == NTHREADS_SCAN - 1) g_M = wsum[31] + incl;
}

// ---------------- kernel 1: gather + L2 normalize + fp16 ---------------------
__global__ void __launch_bounds__(256)
k_normalize(const float* __restrict__ feats)
{
    const int j = blockIdx.x;
    const int M = g_M;
    const int Mpad = (M + 127) & ~127;
    if (j >= Mpad) return;
    const int t = threadIdx.x;

    if (j >= M) {
        ((uint2*)(g_f16 + (size_t)j * D_DIM))[t] = make_uint2(0, 0);
        if (t == 0) g_lab[j] = 0x80000000;
        return;
    }
    const int src = g_sel[j];
    const float4 a = ((const float4*)(feats + (size_t)src * D_DIM))[t];
    float ss = a.x * a.x + a.y * a.y + a.z * a.z + a.w * a.w;

    __shared__ float red[256];
    red[t] = ss;
    __syncthreads();
    for (int off = 128; off > 0; off >>= 1) {
        if (t < off) red[t] += red[t + off];
        __syncthreads();
    }
    const float inv = 1.0f / fmaxf(sqrtf(red[0]), 1e-12f);

    __half h[4];
    h[0] = __float2half_rn(a.x * inv);
    h[1] = __float2half_rn(a.y * inv);
    h[2] = __float2half_rn(a.z * inv);
    h[3] = __float2half_rn(a.w * inv);
    uint2 hp;
    hp.x = (uint32_t)(*(uint16_t*)&h[0]) | ((uint32_t)(*(uint16_t*)&h[1]) << 16);
    hp.y = (uint32_t)(*(uint16_t*)&h[2]) | ((uint32_t)(*(uint16_t*)&h[3]) << 16);
    ((uint2*)(g_f16 + (size_t)j * D_DIM))[t] = hp;
}

// ---------------- kernel 2: fp16 single-product GEMM (symmetric tiles) -------
#define TILE 128
#define KC 64
#define NCHUNK (D_DIM / KC)                   // 16
#define TILE_BYTES (TILE * 128)               // 16384
#define STAGE_BYTES (2 * TILE_BYTES)          // 32768 (A,B)
#define NSTAGE 3
#define GEMM_SMEM (NSTAGE * STAGE_BYTES)      // 98304 -> 2 CTAs/SM
#define PAD_SENTINEL -1e30f

__device__ __forceinline__ void ldsm4(uint32_t* r, uint32_t addr) {
    asm volatile("ldmatrix.sync.aligned.m8n8.x4.shared.b16 {%0,%1,%2,%3}, [%4];"
                 : "=r"(r[0]), "=r"(r[1]), "=r"(r[2]), "=r"(r[3]) : "r"(addr));
}
__device__ __forceinline__ void mma16816h(float* d, const uint32_t* a, const uint32_t* b) {
    asm volatile(
        "mma.sync.aligned.m16n8k16.row.col.f32.f16.f16.f32 "
        "{%0,%1,%2,%3}, {%4,%5,%6,%7}, {%8,%9}, {%0,%1,%2,%3};"
        : "+f"(d[0]), "+f"(d[1]), "+f"(d[2]), "+f"(d[3])
        : "r"(a[0]), "r"(a[1]), "r"(a[2]), "r"(a[3]), "r"(b[0]), "r"(b[1]));
}

__global__ void __launch_bounds__(256, 2)
k_gemm()
{
    const int M = g_M;
    const int tiles = (M + 127) >> 7;
    const int bx = blockIdx.x, by = blockIdx.y;
    if (by >= tiles || bx > by) return;
    const int ldm = tiles << 7;
    const int rt = by * TILE;
    const int ct = bx * TILE;
    const int tid = threadIdx.x;
    const int lane = tid & 31;
    const int wid = tid >> 5;
    const int wm = wid >> 1;
    const int wn = wid & 1;

    extern __shared__ __align__(1024) char smc[];
    const uint32_t tb = smem_u32(smc);

    auto load_chunk = [&](int kc, int stage) {
        const uint32_t sb = tb + stage * STAGE_BYTES;
        const int kb = kc * KC;
#pragma unroll
        for (int i = 0; i < 8; i++) {
            const int c = tid + i * 256;
            const int tix = c >> 10;
            const int r   = (c >> 3) & 127;
            const int seg = c & 7;
            const __half* src = g_f16 + (size_t)((tix ? ct : rt) + r) * D_DIM + kb + seg * 8;
            uint32_t dst = sb + tix * TILE_BYTES + r * 128 + ((seg ^ (r & 7)) << 4);
            asm volatile("cp.async.cg.shared.global [%0], [%1], 16;" :: "r"(dst), "l"(src));
        }
        asm volatile("cp.async.commit_group;");
    };

    float acc[2][8][4];
#pragma unroll
    for (int mf = 0; mf < 2; mf++)
#pragma unroll
        for (int nf = 0; nf < 8; nf++)
#pragma unroll
            for (int i = 0; i < 4; i++) acc[mf][nf][i] = 0.0f;

    load_chunk(0, 0);
    load_chunk(1, 1);
    load_chunk(2, 2);

    for (int k = 0; k < NCHUNK; k++) {
        if (k + 3 <= NCHUNK)      asm volatile("cp.async.wait_group 2;" ::: "memory");
        else if (k + 2 == NCHUNK) asm volatile("cp.async.wait_group 1;" ::: "memory");
        else                      asm volatile("cp.async.wait_group 0;" ::: "memory");
        __syncthreads();

        const int st = k % NSTAGE;
        const uint32_t A = tb + st * STAGE_BYTES;
        const uint32_t B = A + TILE_BYTES;

#pragma unroll
        for (int ks = 0; ks < 4; ks++) {
            uint32_t ah[2][4];
#pragma unroll
            for (int mf = 0; mf < 2; mf++) {
                const int row = wm * 32 + mf * 16 + (lane & 15);
                const int seg = ks * 2 + (lane >> 4);
                ldsm4(ah[mf], A + row * 128 + ((seg ^ (row & 7)) << 4));
            }
            uint32_t bh[4][4];
#pragma unroll
            for (int nq = 0; nq < 4; nq++) {
                const int row = wn * 64 + nq * 16 + (lane & 7) + ((lane >> 4) << 3);
                const int seg = ks * 2 + ((lane >> 3) & 1);
                ldsm4(bh[nq], B + row * 128 + ((seg ^ (row & 7)) << 4));
            }
#pragma unroll
            for (int mf = 0; mf < 2; mf++)
#pragma unroll
                for (int nf = 0; nf < 8; nf++)
                    mma16816h(acc[mf][nf], ah[mf], &bh[nf >> 1][(nf & 1) * 2]);
        }
        __syncthreads();
        if (k + 3 < NCHUNK) load_chunk(k + 3, st);
    }

#pragma unroll
    for (int mf = 0; mf < 2; mf++)
#pragma unroll
        for (int nf = 0; nf < 8; nf++) {
            const int r0 = rt + wm * 32 + mf * 16 + (lane >> 2);
            const int c0 = ct + wn * 64 + nf * 8 + (lane & 3) * 2;
            float v0 = (c0     >= M) ? PAD_SENTINEL : acc[mf][nf][0];
            float v1 = (c0 + 1 >= M) ? PAD_SENTINEL : acc[mf][nf][1];
            float v2 = (c0     >= M) ? PAD_SENTINEL : acc[mf][nf][2];
            float v3 = (c0 + 1 >= M) ? PAD_SENTINEL : acc[mf][nf][3];
            *(float2*)(g_sim + (size_t)r0 * ldm + c0)       = make_float2(v0, v1);
            *(float2*)(g_sim + (size_t)(r0 + 8) * ldm + c0) = make_float2(v2, v3);
        }

    if (bx == by) {
        __syncthreads();
        if (tid < 128) {
            const int d = rt + tid;
            if (d < M) g_sim[(size_t)d * ldm + d] = 1.0f;
        }
    } else {
        float* S = (float*)smc;      // [128][136]
#pragma unroll
        for (int mf = 0; mf < 2; mf++)
#pragma unroll
            for (int nf = 0; nf < 8; nf++) {
                const int rl = wm * 32 + mf * 16 + (lane >> 2);
                const int cl = wn * 64 + nf * 8 + (lane & 3) * 2;
                S[cl * 136 + rl]           = acc[mf][nf][0];
                S[(cl + 1) * 136 + rl]     = acc[mf][nf][1];
                S[cl * 136 + rl + 8]       = acc[mf][nf][2];
                S[(cl + 1) * 136 + rl + 8] = acc[mf][nf][3];
            }
        __syncthreads();
        for (int i = tid; i < 128 * 32; i += 256) {
            const int row = i >> 5;
            const int c4  = (i & 31) * 4;
            float4 v = make_float4(S[row * 136 + c4], S[row * 136 + c4 + 1],
                                   S[row * 136 + c4 + 2], S[row * 136 + c4 + 3]);
            if (rt + c4     >= M) v.x = PAD_SENTINEL;
            if (rt + c4 + 1 >= M) v.y = PAD_SENTINEL;
            if (rt + c4 + 2 >= M) v.z = PAD_SENTINEL;
            if (rt + c4 + 3 >= M) v.w = PAD_SENTINEL;
            *(float4*)(g_sim + (size_t)(ct + row) * ldm + rt + c4) = v;
        }
    }
}

// ---------------- kernel 3: per-row epilogue (R10 geometry, MLP-unrolled) ----
__device__ __forceinline__ void rl_stats(const float4 sv, const int4 lv, int labr,
                                         float C1, float INF,
                                         float& minpos, float& maxneg, int& cnt)
{
    const bool b0 = (lv.x == labr), b1 = (lv.y == labr);
    const bool b2 = (lv.z == labr), b3 = (lv.w == labr);
    cnt += (int)b0 + (int)b1 + (int)b2 + (int)b3;
    minpos = fminf(minpos, (b0 && sv.x < C1) ? sv.x : INF);
    minpos = fminf(minpos, (b1 && sv.y < C1) ? sv.y : INF);
    minpos = fminf(minpos, (b2 && sv.z < C1) ? sv.z : INF);
    minpos = fminf(minpos, (b3 && sv.w < C1) ? sv.w : INF);
    maxneg = fmaxf(maxneg, b0 ? -INF : sv.x);
    maxneg = fmaxf(maxneg, b1 ? -INF : sv.y);
    maxneg = fmaxf(maxneg, b2 ? -INF : sv.z);
    maxneg = fmaxf(maxneg, b3 ? -INF : sv.w);
}
__device__ __forceinline__ void rl_sums(const float4 sv, const int4 lv, int labr,
                                        float C1, float mp, float mn,
                                        float& psum, float& nsum)
{
    if (lv.x == labr) { if (sv.x < C1 && sv.x - 0.1f < mn) psum += __expf(-2.0f * (sv.x - 0.5f)); }
    else              { if (sv.x + 0.1f > mp)             nsum += __expf(40.0f * (sv.x - 0.5f)); }
    if (lv.y == labr) { if (sv.y < C1 && sv.y - 0.1f < mn) psum += __expf(-2.0f * (sv.y - 0.5f)); }
    else              { if (sv.y + 0.1f > mp)             nsum += __expf(40.0f * (sv.y - 0.5f)); }
    if (lv.z == labr) { if (sv.z < C1 && sv.z - 0.1f < mn) psum += __expf(-2.0f * (sv.z - 0.5f)); }
    else              { if (sv.z + 0.1f > mp)             nsum += __expf(40.0f * (sv.z - 0.5f)); }
    if (lv.w == labr) { if (sv.w < C1 && sv.w - 0.1f < mn) psum += __expf(-2.0f * (sv.w - 0.5f)); }
    else              { if (sv.w + 0.1f > mp)             nsum += __expf(40.0f * (sv.w - 0.5f)); }
}

__global__ void __launch_bounds__(256)
k_rowloss()
{
    const int M = g_M;
    if ((int)blockIdx.x * 2 >= M) return;
    const int Mpad = (M + 127) & ~127;
    const int Mpad4 = Mpad >> 2;
    const int t = threadIdx.x;
    const int lane = t & 31;
    const int wid = t >> 5;          // 0..7
    const int grp = wid >> 2;        // 0..1 : row group
    const int gtid = t & 127;        // 0..127 within group
    const int r = blockIdx.x * 2 + grp;
    const bool active = (r < M);

    __shared__ float sm_min[8], sm_max[8], sm_p[8], sm_n[8];
    __shared__ int sm_cnt[8];

    const int labr = active ? __ldg(&g_lab[r]) : 0;
    const float4* __restrict__ row4 = (const float4*)(g_sim + (size_t)r * (size_t)Mpad);
    const int4* __restrict__ lab4 = (const int4*)g_lab;
    const float INF = __int_as_float(0x7f800000);
    const float C1 = 1.0f - 1e-5f;

    // pass 1: 2-way unrolled, both iterations' loads in flight (MLP boost)
    float minpos = INF, maxneg = -INF;
    int cnt = 0;
    if (active) {
        int q = gtid;
        for (; q + 128 < Mpad4; q += 256) {
            const float4 sv0 = __ldg(row4 + q);
            const int4  lv0 = __ldg(lab4 + q);
            const float4 sv1 = __ldg(row4 + q + 128);
            const int4  lv1 = __ldg(lab4 + q + 128);
            rl_stats(sv0, lv0, labr, C1, INF, minpos, maxneg, cnt);
            rl_stats(sv1, lv1, labr, C1, INF, minpos, maxneg, cnt);
        }
        if (q < Mpad4) {
            const float4 sv0 = __ldg(row4 + q);
            const int4  lv0 = __ldg(lab4 + q);
            rl_stats(sv0, lv0, labr, C1, INF, minpos, maxneg, cnt);
        }
    }
#pragma unroll
    for (int o = 16; o; o >>= 1) {
        minpos = fminf(minpos, __shfl_xor_sync(0xffffffffu, minpos, o));
        maxneg = fmaxf(maxneg, __shfl_xor_sync(0xffffffffu, maxneg, o));
        cnt += __shfl_xor_sync(0xffffffffu, cnt, o);
    }
    if (lane == 0) { sm_min[wid] = minpos; sm_max[wid] = maxneg; sm_cnt[wid] = cnt; }
    __syncthreads();
    const int gb = grp * 4;
    float mp = INF, mn = -INF;
    int c = 0;
#pragma unroll
    for (int q = 0; q < 4; q++) {
        mp = fminf(mp, sm_min[gb + q]);
        mn = fmaxf(mn, sm_max[gb + q]);
        c += sm_cnt[gb + q];
    }
    const bool valid = active && (c > 1) && (mn > mp - 0.1f);

    // pass 2: same 2-way unrolled load schedule
    float psum = 0.f, nsum = 0.f;
    if (valid) {
        int q = gtid;
        for (; q + 128 < Mpad4; q += 256) {
            const float4 sv0 = __ldg(row4 + q);
            const int4  lv0 = __ldg(lab4 + q);
            const float4 sv1 = __ldg(row4 + q + 128);
            const int4  lv1 = __ldg(lab4 + q + 128);
            rl_sums(sv0, lv0, labr, C1, mp, mn, psum, nsum);
            rl_sums(sv1, lv1, labr, C1, mp, mn, psum, nsum);
        }
        if (q < Mpad4) {
            const float4 sv0 = __ldg(row4 + q);
            const int4  lv0 = __ldg(lab4 + q);
            rl_sums(sv0, lv0, labr, C1, mp, mn, psum, nsum);
        }
    }
#pragma unroll
    for (int o = 16; o; o >>= 1) {
        psum += __shfl_xor_sync(0xffffffffu, psum, o);
        nsum += __shfl_xor_sync(0xffffffffu, nsum, o);
    }
    if (lane == 0) { sm_p[wid] = psum; sm_n[wid] = nsum; }
    __syncthreads();
    if (active && gtid == 0) {
        if (!valid) {
            g_rowloss[r] = 0.0f;
        } else {
            float P = sm_p[gb] + sm_p[gb + 1] + sm_p[gb + 2] + sm_p[gb + 3];
            float N = sm_n[gb] + sm_n[gb + 1] + sm_n[gb + 2] + sm_n[gb + 3];
            g_rowloss[r] = log1pf(P) / 2.0f + log1pf(N) / 40.0f;
        }
    }
}

// ---------------- kernel 4: deterministic final sum --------------------------
__global__ void __launch_bounds__(256)
k_finalize(float* __restrict__ out)
{
    const int M = g_M;
    const int t = threadIdx.x;
    float acc = 0.f;
    for (int i = t; i < M; i += 256) acc += g_rowloss[i];
    __shared__ float red[256];
    red[t] = acc;
    __syncthreads();
    for (int off = 128; off > 0; off >>= 1) {
        if (t < off) red[t] += red[t + off];
        __syncthreads();
    }
    if (t == 0) out[0] = red[0] / (float)B_ROWS;
}

// ---------------- launcher ---------------------------------------------------
extern "C" void kernel_launch(void* const* d_in, const int* in_sizes, int n_in,
                              void* d_out, int out_size)
{
    const float* feats  = (const float*)d_in[0];
    const void*  labels = d_in[1];
    const float* score  = (const float*)d_in[2];
    const int*   tidx   = (const int*)d_in[3];
    float* out = (float*)d_out;

    cudaFuncSetAttribute(k_gemm, cudaFuncAttributeMaxDynamicSharedMemorySize, GEMM_SMEM);

    k_select<<<1, NTHREADS_SCAN>>>(score, labels, tidx);
    k_normalize<<<B_ROWS, 256>>>(feats);
    dim3 grid(B_ROWS / TILE, B_ROWS / TILE);
    k_gemm<<<grid, 256, GEMM_SMEM>>>();
    k_rowloss<<<B_ROWS / 2, 256>>>();
    k_finalize<<<1, 256>>>(out);
}